// round 7
// baseline (speedup 1.0000x reference)
#include <cuda_runtime.h>
#include <cuda_fp16.h>
#include <math.h>
#include <stdint.h>

#define N_NODES 50000
#define N_EDGES 800000
#define H 128
#define LN_EPS 1e-5f

#define AS2_STRIDE 68    // half2 units per A row (64 data + 4 pad)
#define BS2_STRIDE 136   // half2 units per B k-pair row (128 data + 8 pad)
#define CS_STRIDE  132   // float units per C row in epilogue staging
#define SMEM_A2 (64 * AS2_STRIDE * 4)
#define SMEM_B2 (64 * BS2_STRIDE * 4)
#define SMEM_EDGE (SMEM_A2 + SMEM_B2)            // 52224 B

// Static device scratch
__device__ float g_PQ[(size_t)N_NODES * 256];    // P | Q per node
__device__ int   g_perm[N_EDGES];                // receiver-sorted slot -> edge id
__device__ int   g_count[N_NODES];
__device__ int   g_cursor[N_NODES];

// Pack two floats into f16x2: lo half = a, hi half = b.
__device__ __forceinline__ uint32_t pack_h2(float a, float b) {
    uint32_t u;
    asm("cvt.rn.f16x2.f32 %0, %1, %2;" : "=r"(u) : "f"(b), "f"(a));
    return u;
}

__device__ __forceinline__ void mma_f16(float d[4], uint32_t a0, uint32_t a1,
                                        uint32_t a2, uint32_t a3,
                                        uint32_t b0, uint32_t b1) {
    asm volatile(
        "mma.sync.aligned.m16n8k16.row.col.f32.f16.f16.f32 "
        "{%0,%1,%2,%3}, {%4,%5,%6,%7}, {%8,%9}, {%0,%1,%2,%3};"
        : "+f"(d[0]), "+f"(d[1]), "+f"(d[2]), "+f"(d[3])
        : "r"(a0), "r"(a1), "r"(a2), "r"(a3), "r"(b0), "r"(b1));
}

// ---------------------------------------------------------------------------
// CSR-lite: receiver-sorted permutation
// ---------------------------------------------------------------------------
__global__ void zero_count_kernel() {
    int i = blockIdx.x * blockDim.x + threadIdx.x;
    if (i < N_NODES) g_count[i] = 0;
}

__global__ void hist_kernel(const int* __restrict__ receivers) {
    int i = blockIdx.x * blockDim.x + threadIdx.x;
    if (i < N_EDGES) atomicAdd(&g_count[receivers[i]], 1);
}

// Single block, 1024 threads, 50 nodes/thread exclusive scan -> g_cursor
__global__ __launch_bounds__(1024) void scan_kernel() {
    __shared__ int warp_sums[32];
    const int t = threadIdx.x;
    const int lane = t & 31, warp = t >> 5;
    const int base = t * 50;

    int s = 0;
    for (int i = 0; i < 50; ++i) {
        int idx = base + i;
        if (idx < N_NODES) s += g_count[idx];
    }
    int v = s;
#pragma unroll
    for (int off = 1; off < 32; off <<= 1) {
        int n = __shfl_up_sync(0xffffffffu, v, off);
        if (lane >= off) v += n;
    }
    if (lane == 31) warp_sums[warp] = v;
    __syncthreads();
    if (warp == 0) {
        int w = warp_sums[lane];
#pragma unroll
        for (int off = 1; off < 32; off <<= 1) {
            int n = __shfl_up_sync(0xffffffffu, w, off);
            if (lane >= off) w += n;
        }
        warp_sums[lane] = w;
    }
    __syncthreads();
    int excl = (warp == 0 ? 0 : warp_sums[warp - 1]) + (v - s);
    for (int i = 0; i < 50; ++i) {
        int idx = base + i;
        if (idx < N_NODES) {
            g_cursor[idx] = excl;
            excl += g_count[idx];
        }
    }
}

__global__ void scatter_kernel(const int* __restrict__ receivers) {
    int i = blockIdx.x * blockDim.x + threadIdx.x;
    if (i < N_EDGES) {
        int pos = atomicAdd(&g_cursor[receivers[i]], 1);
        g_perm[pos] = i;
    }
}

// ---------------------------------------------------------------------------
// Node projection: P = x@Ws + b1 (half 0), Q = x@Wr (half 1). fp32.
// ---------------------------------------------------------------------------
__global__ __launch_bounds__(256) void proj_kernel(const float* __restrict__ x,
                                                   const float* __restrict__ W1,
                                                   const float* __restrict__ b1) {
    __shared__ float As[128 * 64];
    __shared__ float Bs[32 * 128];

    const int tid  = threadIdx.x;
    const int half = blockIdx.y;
    const int m0   = blockIdx.x * 64;
    const int eg   = tid >> 5;
    const int og   = tid & 31;

#pragma unroll
    for (int it = 0; it < 8; ++it) {
        int idx = tid + it * 256;
        int m   = idx & 63;
        int kg  = idx >> 6;
        int n   = m0 + m;
        float4 v = make_float4(0.f, 0.f, 0.f, 0.f);
        if (n < N_NODES) v = *(const float4*)(x + (size_t)n * H + kg * 4);
        As[(kg * 4 + 0) * 64 + m] = v.x;
        As[(kg * 4 + 1) * 64 + m] = v.y;
        As[(kg * 4 + 2) * 64 + m] = v.z;
        As[(kg * 4 + 3) * 64 + m] = v.w;
    }

    float4 acc[8];
#pragma unroll
    for (int i = 0; i < 8; ++i) acc[i] = make_float4(0.f, 0.f, 0.f, 0.f);

    const float* B = W1 + (size_t)half * 128 * H;

    for (int kc = 0; kc < 4; ++kc) {
        __syncthreads();
#pragma unroll
        for (int it = 0; it < 4; ++it) {
            int idx = tid + it * 256;
            int o4  = idx & 31;
            int r   = idx >> 5;
            *(float4*)(Bs + r * 128 + o4 * 4) =
                *(const float4*)(B + (size_t)(kc * 32 + r) * H + o4 * 4);
        }
        __syncthreads();
#pragma unroll
        for (int k = 0; k < 32; ++k) {
            const float* ap = As + (kc * 32 + k) * 64 + eg * 8;
            float4 a0 = *(const float4*)(ap);
            float4 a1 = *(const float4*)(ap + 4);
            float4 b  = *(const float4*)(Bs + k * 128 + og * 4);
            float ar[8] = {a0.x, a0.y, a0.z, a0.w, a1.x, a1.y, a1.z, a1.w};
#pragma unroll
            for (int i = 0; i < 8; ++i) {
                acc[i].x += ar[i] * b.x;
                acc[i].y += ar[i] * b.y;
                acc[i].z += ar[i] * b.z;
                acc[i].w += ar[i] * b.w;
            }
        }
    }

    float4 bias = make_float4(0.f, 0.f, 0.f, 0.f);
    if (half == 0) bias = *(const float4*)(b1 + og * 4);

#pragma unroll
    for (int i = 0; i < 8; ++i) {
        int n = m0 + eg * 8 + i;
        if (n < N_NODES) {
            float4 v;
            v.x = acc[i].x + bias.x;
            v.y = acc[i].y + bias.y;
            v.z = acc[i].z + bias.z;
            v.w = acc[i].w + bias.w;
            *(float4*)(g_PQ + (size_t)n * 256 + half * 128 + og * 4) = v;
        }
    }
}

// ---------------------------------------------------------------------------
// out = x (residual preload)
// ---------------------------------------------------------------------------
__global__ void init_kernel(float* __restrict__ out, const float* __restrict__ x) {
    int i = blockIdx.x * blockDim.x + threadIdx.x;
    if (i < N_NODES * H / 4) ((float4*)out)[i] = ((const float4*)x)[i];
}

// ---------------------------------------------------------------------------
// Edge GEMM (fp16 mma, fp32 accum), edges in receiver-sorted order.
// Epilogue merges consecutive same-receiver edges before red.v4.
// ---------------------------------------------------------------------------
__global__ __launch_bounds__(256) void edge_kernel(const float* __restrict__ ef,
                                                   const int* __restrict__ senders,
                                                   const int* __restrict__ receivers,
                                                   const float* __restrict__ W1,
                                                   float* __restrict__ out) {
    extern __shared__ float smem_dyn[];
    uint32_t* As2 = (uint32_t*)smem_dyn;                      // [64][AS2_STRIDE]
    uint32_t* Bs2 = (uint32_t*)smem_dyn + 64 * AS2_STRIDE;    // [64][BS2_STRIDE]
    __shared__ int sperm[64];

    const int tid = threadIdx.x;
    const int e0  = blockIdx.x * 64;

    if (tid < 64) sperm[tid] = g_perm[e0 + tid];
    __syncthreads();

    // A tile: gathered edge_feat rows (512B contiguous each), fp16 k-pairs
#pragma unroll
    for (int it = 0; it < 8; ++it) {
        int idx = tid + it * 256;
        int e   = idx >> 5;
        int kg  = idx & 31;
        float4 v = *(const float4*)(ef + (size_t)sperm[e] * H + kg * 4);
        uint32_t* dst = As2 + e * AS2_STRIDE + kg * 2;
        dst[0] = pack_h2(v.x, v.y);
        dst[1] = pack_h2(v.z, v.w);
    }

    // B tile (We = rows 256..383 of W1) as half2 (k even, k odd) per n
    const float* B = W1 + (size_t)256 * H;
#pragma unroll
    for (int it = 0; it < 8; ++it) {
        int idx = tid + it * 256;
        int kp  = idx >> 5;
        int o4  = idx & 31;
        float4 ve = *(const float4*)(B + (size_t)(2 * kp)     * H + o4 * 4);
        float4 vo = *(const float4*)(B + (size_t)(2 * kp + 1) * H + o4 * 4);
        uint32_t* dst = Bs2 + kp * BS2_STRIDE + o4 * 4;
        dst[0] = pack_h2(ve.x, vo.x);
        dst[1] = pack_h2(ve.y, vo.y);
        dst[2] = pack_h2(ve.z, vo.z);
        dst[3] = pack_h2(ve.w, vo.w);
    }
    __syncthreads();

    const int lane = tid & 31;
    const int wid  = tid >> 5;
    const int g    = lane >> 2;
    const int tig  = lane & 3;
    const int m_base = (wid & 3) * 16;
    const int n_base = (wid >> 2) * 64;

    float d[8][4];
#pragma unroll
    for (int j = 0; j < 8; ++j)
#pragma unroll
        for (int i = 0; i < 4; ++i) d[j][i] = 0.f;

#pragma unroll
    for (int ks = 0; ks < 8; ++ks) {
        const int kp0 = ks * 8;
        const uint32_t* ar = As2 + (m_base + g) * AS2_STRIDE + kp0 + tig;
        uint32_t a0 = ar[0];
        uint32_t a2 = ar[4];
        uint32_t a1 = ar[8 * AS2_STRIDE];
        uint32_t a3 = ar[8 * AS2_STRIDE + 4];
        const uint32_t* br = Bs2 + (kp0 + tig) * BS2_STRIDE + n_base + g;
#pragma unroll
        for (int j = 0; j < 8; ++j) {
            uint32_t b0 = br[j * 8];
            uint32_t b1 = br[4 * BS2_STRIDE + j * 8];
            mma_f16(d[j], a0, a1, a2, a3, b0, b1);
        }
    }

    __syncthreads();

    float* Cs = smem_dyn;   // [64][CS_STRIDE]
#pragma unroll
    for (int j = 0; j < 8; ++j) {
        int c = n_base + j * 8 + 2 * tig;
        *(float2*)(Cs + (m_base + g) * CS_STRIDE + c)     = make_float2(d[j][0], d[j][1]);
        *(float2*)(Cs + (m_base + g + 8) * CS_STRIDE + c) = make_float2(d[j][2], d[j][3]);
    }
    __syncthreads();

    // Epilogue: warp handles 8 consecutive sorted edges; merge same-receiver
    // runs in registers, then one red.v4 per distinct receiver.
    const int eg = tid >> 5;
    const int og = tid & 31;
    int prev_r = -1;
    float4 accm = make_float4(0.f, 0.f, 0.f, 0.f);
#pragma unroll
    for (int i = 0; i < 8; ++i) {
        int el = eg * 8 + i;
        int e  = sperm[el];
        int s  = senders[e];
        int r  = receivers[e];
        float4 m = *(const float4*)(Cs + el * CS_STRIDE + og * 4);
        float4 p = *(const float4*)(g_PQ + (size_t)s * 256 + og * 4);
        float4 q = *(const float4*)(g_PQ + (size_t)r * 256 + 128 + og * 4);
        m.x = fmaxf(m.x + p.x + q.x, 0.f);
        m.y = fmaxf(m.y + p.y + q.y, 0.f);
        m.z = fmaxf(m.z + p.z + q.z, 0.f);
        m.w = fmaxf(m.w + p.w + q.w, 0.f);
        if (r != prev_r) {
            if (prev_r >= 0) {
                float* dst = out + (size_t)prev_r * H + og * 4;
                asm volatile("red.global.add.v4.f32 [%0], {%1,%2,%3,%4};"
                             :: "l"(dst), "f"(accm.x), "f"(accm.y), "f"(accm.z), "f"(accm.w)
                             : "memory");
            }
            accm = m;
            prev_r = r;
        } else {
            accm.x += m.x; accm.y += m.y; accm.z += m.z; accm.w += m.w;
        }
    }
    {
        float* dst = out + (size_t)prev_r * H + og * 4;
        asm volatile("red.global.add.v4.f32 [%0], {%1,%2,%3,%4};"
                     :: "l"(dst), "f"(accm.x), "f"(accm.y), "f"(accm.z), "f"(accm.w)
                     : "memory");
    }
}

// ---------------------------------------------------------------------------
// In-place LayerNorm, one warp per row
// ---------------------------------------------------------------------------
__global__ __launch_bounds__(256) void ln_kernel(float* __restrict__ out,
                                                 const float* __restrict__ gamma,
                                                 const float* __restrict__ beta) {
    int warp = threadIdx.x >> 5;
    int lane = threadIdx.x & 31;
    int row  = blockIdx.x * 8 + warp;
    if (row >= N_NODES) return;

    float4 h = *(const float4*)(out + (size_t)row * H + lane * 4);
    float s  = h.x + h.y + h.z + h.w;
    float s2 = h.x * h.x + h.y * h.y + h.z * h.z + h.w * h.w;
#pragma unroll
    for (int off = 16; off > 0; off >>= 1) {
        s  += __shfl_xor_sync(0xffffffffu, s, off);
        s2 += __shfl_xor_sync(0xffffffffu, s2, off);
    }
    float mean = s * (1.f / H);
    float var  = s2 * (1.f / H) - mean * mean;
    float rstd = rsqrtf(var + LN_EPS);

    float4 g = *(const float4*)(gamma + lane * 4);
    float4 b = *(const float4*)(beta + lane * 4);
    float4 o;
    o.x = g.x * (h.x - mean) * rstd + b.x;
    o.y = g.y * (h.y - mean) * rstd + b.y;
    o.z = g.z * (h.z - mean) * rstd + b.z;
    o.w = g.w * (h.w - mean) * rstd + b.w;
    *(float4*)(out + (size_t)row * H + lane * 4) = o;
}

// ---------------------------------------------------------------------------
extern "C" void kernel_launch(void* const* d_in, const int* in_sizes, int n_in,
                              void* d_out, int out_size) {
    const float* x         = (const float*)d_in[0];
    const int*   senders   = (const int*)d_in[1];
    const int*   receivers = (const int*)d_in[2];
    const float* ef        = (const float*)d_in[3];
    const float* W1        = (const float*)d_in[4];
    const float* b1        = (const float*)d_in[5];
    const float* gamma     = (const float*)d_in[6];
    const float* beta      = (const float*)d_in[7];
    float*       out       = (float*)d_out;

    cudaFuncSetAttribute(edge_kernel, cudaFuncAttributeMaxDynamicSharedMemorySize,
                         SMEM_EDGE);

    zero_count_kernel<<<(N_NODES + 255) / 256, 256>>>();
    hist_kernel<<<(N_EDGES + 255) / 256, 256>>>(receivers);
    scan_kernel<<<1, 1024>>>();
    scatter_kernel<<<(N_EDGES + 255) / 256, 256>>>(receivers);
    proj_kernel<<<dim3((N_NODES + 63) / 64, 2), 256>>>(x, W1, b1);
    init_kernel<<<(N_NODES * H / 4 + 255) / 256, 256>>>(out, x);
    edge_kernel<<<N_EDGES / 64, 256, SMEM_EDGE>>>(ef, senders, receivers, W1, out);
    ln_kernel<<<N_NODES / 8, 256>>>(out, gamma, beta);
}

// round 8
// speedup vs baseline: 1.3492x; 1.3492x over previous
#include <cuda_runtime.h>
#include <cuda_fp16.h>
#include <math.h>
#include <stdint.h>

#define N_NODES 50000
#define N_EDGES 800000
#define H 128
#define LN_EPS 1e-5f

#define AS2_STRIDE 68    // half2 units per A row (64 data + 4 pad)
#define BS2_STRIDE 136   // half2 units per B k-pair row (128 data + 8 pad)
#define CS_STRIDE  132   // float units per C row in epilogue staging
#define SMEM_A2 (64 * AS2_STRIDE * 4)
#define SMEM_B2 (64 * BS2_STRIDE * 4)
#define SMEM_EDGE (SMEM_A2 + SMEM_B2)            // 52224 B

// Static device scratch
__device__ float    g_PQ[(size_t)N_NODES * 256];   // P | Q per node (fp32)
__device__ uint32_t g_Wh[64 * BS2_STRIDE];         // We pre-packed fp16 k-pairs

// Pack two floats into f16x2: lo half = a, hi half = b.
__device__ __forceinline__ uint32_t pack_h2(float a, float b) {
    uint32_t u;
    asm("cvt.rn.f16x2.f32 %0, %1, %2;" : "=r"(u) : "f"(b), "f"(a));
    return u;
}

__device__ __forceinline__ void mma_f16(float d[4], uint32_t a0, uint32_t a1,
                                        uint32_t a2, uint32_t a3,
                                        uint32_t b0, uint32_t b1) {
    asm volatile(
        "mma.sync.aligned.m16n8k16.row.col.f32.f16.f16.f32 "
        "{%0,%1,%2,%3}, {%4,%5,%6,%7}, {%8,%9}, {%0,%1,%2,%3};"
        : "+f"(d[0]), "+f"(d[1]), "+f"(d[2]), "+f"(d[3])
        : "r"(a0), "r"(a1), "r"(a2), "r"(a3), "r"(b0), "r"(b1));
}

// ---------------------------------------------------------------------------
// Kernel 0: pack We (rows 256..383 of W1) into fp16 k-pair layout, once.
// Layout identical to the edge kernel's SMEM B tile.
// ---------------------------------------------------------------------------
__global__ __launch_bounds__(256) void pack_w_kernel(const float* __restrict__ W1) {
    const int tid = threadIdx.x;
    const float* B = W1 + (size_t)256 * H;
#pragma unroll
    for (int it = 0; it < 8; ++it) {
        int idx = tid + it * 256;
        int kp  = idx >> 5;          // k-pair 0..63
        int o4  = idx & 31;          // n group
        float4 ve = *(const float4*)(B + (size_t)(2 * kp)     * H + o4 * 4);
        float4 vo = *(const float4*)(B + (size_t)(2 * kp + 1) * H + o4 * 4);
        uint32_t* dst = g_Wh + kp * BS2_STRIDE + o4 * 4;
        dst[0] = pack_h2(ve.x, vo.x);
        dst[1] = pack_h2(ve.y, vo.y);
        dst[2] = pack_h2(ve.z, vo.z);
        dst[3] = pack_h2(ve.w, vo.w);
    }
}

// ---------------------------------------------------------------------------
// Kernel 1: node projection (fp32). half 0 -> P = x@Ws + b1 AND out = x
// (residual preload folded in). half 1 -> Q = x@Wr.
// ---------------------------------------------------------------------------
__global__ __launch_bounds__(256) void proj_kernel(const float* __restrict__ x,
                                                   const float* __restrict__ W1,
                                                   const float* __restrict__ b1,
                                                   float* __restrict__ out) {
    __shared__ float As[128 * 64];
    __shared__ float Bs[32 * 128];

    const int tid  = threadIdx.x;
    const int half = blockIdx.y;
    const int m0   = blockIdx.x * 64;
    const int eg   = tid >> 5;
    const int og   = tid & 31;

#pragma unroll
    for (int it = 0; it < 8; ++it) {
        int idx = tid + it * 256;
        int m   = idx & 63;
        int kg  = idx >> 6;
        int n   = m0 + m;
        float4 v = make_float4(0.f, 0.f, 0.f, 0.f);
        if (n < N_NODES) {
            v = *(const float4*)(x + (size_t)n * H + kg * 4);
            if (half == 0) *(float4*)(out + (size_t)n * H + kg * 4) = v;  // out = x
        }
        As[(kg * 4 + 0) * 64 + m] = v.x;
        As[(kg * 4 + 1) * 64 + m] = v.y;
        As[(kg * 4 + 2) * 64 + m] = v.z;
        As[(kg * 4 + 3) * 64 + m] = v.w;
    }

    float4 acc[8];
#pragma unroll
    for (int i = 0; i < 8; ++i) acc[i] = make_float4(0.f, 0.f, 0.f, 0.f);

    const float* B = W1 + (size_t)half * 128 * H;

    for (int kc = 0; kc < 4; ++kc) {
        __syncthreads();
#pragma unroll
        for (int it = 0; it < 4; ++it) {
            int idx = tid + it * 256;
            int o4  = idx & 31;
            int r   = idx >> 5;
            *(float4*)(Bs + r * 128 + o4 * 4) =
                *(const float4*)(B + (size_t)(kc * 32 + r) * H + o4 * 4);
        }
        __syncthreads();
#pragma unroll
        for (int k = 0; k < 32; ++k) {
            const float* ap = As + (kc * 32 + k) * 64 + eg * 8;
            float4 a0 = *(const float4*)(ap);
            float4 a1 = *(const float4*)(ap + 4);
            float4 b  = *(const float4*)(Bs + k * 128 + og * 4);
            float ar[8] = {a0.x, a0.y, a0.z, a0.w, a1.x, a1.y, a1.z, a1.w};
#pragma unroll
            for (int i = 0; i < 8; ++i) {
                acc[i].x += ar[i] * b.x;
                acc[i].y += ar[i] * b.y;
                acc[i].z += ar[i] * b.z;
                acc[i].w += ar[i] * b.w;
            }
        }
    }

    float4 bias = make_float4(0.f, 0.f, 0.f, 0.f);
    if (half == 0) bias = *(const float4*)(b1 + og * 4);

#pragma unroll
    for (int i = 0; i < 8; ++i) {
        int n = m0 + eg * 8 + i;
        if (n < N_NODES) {
            float4 v;
            v.x = acc[i].x + bias.x;
            v.y = acc[i].y + bias.y;
            v.z = acc[i].z + bias.z;
            v.w = acc[i].w + bias.w;
            *(float4*)(g_PQ + (size_t)n * 256 + half * 128 + og * 4) = v;
        }
    }
}

// ---------------------------------------------------------------------------
// Kernel 2: edge GEMM on fp16 tensor cores (mma.m16n8k16, fp32 accumulate).
// Block tile 64 edges x 128 out, K=128. B tile is a pure copy of g_Wh.
// Epilogue: stage accum -> SMEM, gather P[s]/Q[r] (fp32), relu, red.v4.
// ---------------------------------------------------------------------------
__global__ __launch_bounds__(256) void edge_kernel(const float* __restrict__ ef,
                                                   const int* __restrict__ senders,
                                                   const int* __restrict__ receivers,
                                                   float* __restrict__ out) {
    extern __shared__ float smem_dyn[];
    uint32_t* As2 = (uint32_t*)smem_dyn;                      // [64][AS2_STRIDE]
    uint32_t* Bs2 = (uint32_t*)smem_dyn + 64 * AS2_STRIDE;    // [64][BS2_STRIDE]

    const int tid = threadIdx.x;
    const int e0  = blockIdx.x * 64;

    // B tile: straight 16B copy of pre-packed fp16 weights (L2-resident, 32 KB)
#pragma unroll
    for (int it = 0; it < 8; ++it) {
        int idx = tid + it * 256;
        int kp  = idx >> 5;
        int o4  = idx & 31;
        uint4 v = *(const uint4*)(g_Wh + kp * BS2_STRIDE + o4 * 4);
        *(uint4*)(Bs2 + kp * BS2_STRIDE + o4 * 4) = v;
    }

    // A tile (edge_feat rows e0..e0+63), convert to fp16 k-pairs
#pragma unroll
    for (int it = 0; it < 8; ++it) {
        int idx = tid + it * 256;
        int e   = idx >> 5;
        int kg  = idx & 31;
        float4 v = *(const float4*)(ef + (size_t)(e0 + e) * H + kg * 4);
        uint32_t* dst = As2 + e * AS2_STRIDE + kg * 2;
        dst[0] = pack_h2(v.x, v.y);
        dst[1] = pack_h2(v.z, v.w);
    }
    __syncthreads();

    const int lane = tid & 31;
    const int wid  = tid >> 5;
    const int g    = lane >> 2;
    const int tig  = lane & 3;
    const int m_base = (wid & 3) * 16;
    const int n_base = (wid >> 2) * 64;

    float d[8][4];
#pragma unroll
    for (int j = 0; j < 8; ++j)
#pragma unroll
        for (int i = 0; i < 4; ++i) d[j][i] = 0.f;

#pragma unroll
    for (int ks = 0; ks < 8; ++ks) {
        const int kp0 = ks * 8;
        const uint32_t* ar = As2 + (m_base + g) * AS2_STRIDE + kp0 + tig;
        uint32_t a0 = ar[0];
        uint32_t a2 = ar[4];
        uint32_t a1 = ar[8 * AS2_STRIDE];
        uint32_t a3 = ar[8 * AS2_STRIDE + 4];
        const uint32_t* br = Bs2 + (kp0 + tig) * BS2_STRIDE + n_base + g;
#pragma unroll
        for (int j = 0; j < 8; ++j) {
            uint32_t b0 = br[j * 8];
            uint32_t b1 = br[4 * BS2_STRIDE + j * 8];
            mma_f16(d[j], a0, a1, a2, a3, b0, b1);
        }
    }

    __syncthreads();

    float* Cs = smem_dyn;   // [64][CS_STRIDE]
#pragma unroll
    for (int j = 0; j < 8; ++j) {
        int c = n_base + j * 8 + 2 * tig;
        *(float2*)(Cs + (m_base + g) * CS_STRIDE + c)     = make_float2(d[j][0], d[j][1]);
        *(float2*)(Cs + (m_base + g + 8) * CS_STRIDE + c) = make_float2(d[j][2], d[j][3]);
    }
    __syncthreads();

    // Epilogue: msg = relu(Cs + P[s] + Q[r]); vector-atomic scatter into out[r]
    const int eg = tid >> 5;
    const int og = tid & 31;
#pragma unroll
    for (int i = 0; i < 8; ++i) {
        int el = eg * 8 + i;
        int e  = e0 + el;
        int s  = senders[e];
        int r  = receivers[e];
        float4 m = *(const float4*)(Cs + el * CS_STRIDE + og * 4);
        float4 p = *(const float4*)(g_PQ + (size_t)s * 256 + og * 4);
        float4 q = *(const float4*)(g_PQ + (size_t)r * 256 + 128 + og * 4);
        m.x = fmaxf(m.x + p.x + q.x, 0.f);
        m.y = fmaxf(m.y + p.y + q.y, 0.f);
        m.z = fmaxf(m.z + p.z + q.z, 0.f);
        m.w = fmaxf(m.w + p.w + q.w, 0.f);
        float* dst = out + (size_t)r * H + og * 4;
        asm volatile("red.global.add.v4.f32 [%0], {%1,%2,%3,%4};"
                     :: "l"(dst), "f"(m.x), "f"(m.y), "f"(m.z), "f"(m.w)
                     : "memory");
    }
}

// ---------------------------------------------------------------------------
// Kernel 3: in-place LayerNorm, one warp per row
// ---------------------------------------------------------------------------
__global__ __launch_bounds__(256) void ln_kernel(float* __restrict__ out,
                                                 const float* __restrict__ gamma,
                                                 const float* __restrict__ beta) {
    int warp = threadIdx.x >> 5;
    int lane = threadIdx.x & 31;
    int row  = blockIdx.x * 8 + warp;
    if (row >= N_NODES) return;

    float4 h = *(const float4*)(out + (size_t)row * H + lane * 4);
    float s  = h.x + h.y + h.z + h.w;
    float s2 = h.x * h.x + h.y * h.y + h.z * h.z + h.w * h.w;
#pragma unroll
    for (int off = 16; off > 0; off >>= 1) {
        s  += __shfl_xor_sync(0xffffffffu, s, off);
        s2 += __shfl_xor_sync(0xffffffffu, s2, off);
    }
    float mean = s * (1.f / H);
    float var  = s2 * (1.f / H) - mean * mean;
    float rstd = rsqrtf(var + LN_EPS);

    float4 g = *(const float4*)(gamma + lane * 4);
    float4 b = *(const float4*)(beta + lane * 4);
    float4 o;
    o.x = g.x * (h.x - mean) * rstd + b.x;
    o.y = g.y * (h.y - mean) * rstd + b.y;
    o.z = g.z * (h.z - mean) * rstd + b.z;
    o.w = g.w * (h.w - mean) * rstd + b.w;
    *(float4*)(out + (size_t)row * H + lane * 4) = o;
}

// ---------------------------------------------------------------------------
extern "C" void kernel_launch(void* const* d_in, const int* in_sizes, int n_in,
                              void* d_out, int out_size) {
    const float* x         = (const float*)d_in[0];
    const int*   senders   = (const int*)d_in[1];
    const int*   receivers = (const int*)d_in[2];
    const float* ef        = (const float*)d_in[3];
    const float* W1        = (const float*)d_in[4];
    const float* b1        = (const float*)d_in[5];
    const float* gamma     = (const float*)d_in[6];
    const float* beta      = (const float*)d_in[7];
    float*       out       = (float*)d_out;

    cudaFuncSetAttribute(edge_kernel, cudaFuncAttributeMaxDynamicSharedMemorySize,
                         SMEM_EDGE);

    pack_w_kernel<<<1, 256>>>(W1);
    proj_kernel<<<dim3((N_NODES + 63) / 64, 2), 256>>>(x, W1, b1, out);
    edge_kernel<<<N_EDGES / 64, 256, SMEM_EDGE>>>(ef, senders, receivers, out);
    ln_kernel<<<N_NODES / 8, 256>>>(out, gamma, beta);
}

// round 9
// speedup vs baseline: 1.6557x; 1.2272x over previous
#include <cuda_runtime.h>
#include <cuda_fp16.h>
#include <math.h>
#include <stdint.h>

#define N_NODES 50000
#define N_EDGES 800000
#define H 128
#define LN_EPS 1e-5f

#define AS2_STRIDE 68    // half2 units per A row (64 data + 4 pad)
#define BS2_STRIDE 136   // half2 units per B k-pair row (128 data + 8 pad)
#define CS_STRIDE  132   // float units per C row in epilogue staging
#define SMEM_A2 (64 * AS2_STRIDE * 4)
#define SMEM_B2 (64 * BS2_STRIDE * 4)
#define SMEM_EDGE (SMEM_A2 + SMEM_B2)            // 52224 B

// Static device scratch
// g_PQh: per-node projections in fp16 half2 pairs. [node][128] uint32:
//   0..63  = P = x@Ws + b1  (cols 2c, 2c+1)
//   64..127= Q = x@Wr
__device__ uint32_t g_PQh[(size_t)N_NODES * 128];
// g_Wh: W1 pre-packed fp16 k-pair tiles: [3][64*BS2_STRIDE]  (Ws | Wr | We)
__device__ uint32_t g_Wh[3 * 64 * BS2_STRIDE];

// Pack two floats into f16x2: lo half = a, hi half = b.
__device__ __forceinline__ uint32_t pack_h2(float a, float b) {
    uint32_t u;
    asm("cvt.rn.f16x2.f32 %0, %1, %2;" : "=r"(u) : "f"(b), "f"(a));
    return u;
}

__device__ __forceinline__ float2 h2f2(uint32_t u) {
    __half2 h = *(__half2*)&u;
    return __half22float2(h);
}

__device__ __forceinline__ void mma_f16(float d[4], uint32_t a0, uint32_t a1,
                                        uint32_t a2, uint32_t a3,
                                        uint32_t b0, uint32_t b1) {
    asm volatile(
        "mma.sync.aligned.m16n8k16.row.col.f32.f16.f16.f32 "
        "{%0,%1,%2,%3}, {%4,%5,%6,%7}, {%8,%9}, {%0,%1,%2,%3};"
        : "+f"(d[0]), "+f"(d[1]), "+f"(d[2]), "+f"(d[3])
        : "r"(a0), "r"(a1), "r"(a2), "r"(a3), "r"(b0), "r"(b1));
}

// ---------------------------------------------------------------------------
// Kernel 0: pack all three W1 sections (Ws, Wr, We) into fp16 k-pair layout.
// ---------------------------------------------------------------------------
__global__ __launch_bounds__(256) void pack_w_kernel(const float* __restrict__ W1) {
    const int tid = threadIdx.x;
    for (int sec = 0; sec < 3; ++sec) {
        const float* B = W1 + (size_t)sec * 128 * H;
        uint32_t* W = g_Wh + sec * 64 * BS2_STRIDE;
#pragma unroll
        for (int it = 0; it < 8; ++it) {
            int idx = tid + it * 256;
            int kp  = idx >> 5;
            int o4  = idx & 31;
            float4 ve = *(const float4*)(B + (size_t)(2 * kp)     * H + o4 * 4);
            float4 vo = *(const float4*)(B + (size_t)(2 * kp + 1) * H + o4 * 4);
            uint32_t* dst = W + kp * BS2_STRIDE + o4 * 4;
            dst[0] = pack_h2(ve.x, vo.x);
            dst[1] = pack_h2(ve.y, vo.y);
            dst[2] = pack_h2(ve.z, vo.z);
            dst[3] = pack_h2(ve.w, vo.w);
        }
    }
}

// ---------------------------------------------------------------------------
// Kernel 1: node projection on fp16 tensor cores.
// blockIdx.y = 0: P = x@Ws + b1, also out = x (residual preload).
// blockIdx.y = 1: Q = x@Wr.  Output packed fp16 into g_PQh.
// ---------------------------------------------------------------------------
__global__ __launch_bounds__(256) void proj_kernel(const float* __restrict__ x,
                                                   const float* __restrict__ b1,
                                                   float* __restrict__ out) {
    extern __shared__ float smem_dyn[];
    uint32_t* As2 = (uint32_t*)smem_dyn;
    uint32_t* Bs2 = (uint32_t*)smem_dyn + 64 * AS2_STRIDE;

    const int tid  = threadIdx.x;
    const int half = blockIdx.y;
    const int m0   = blockIdx.x * 64;

    // B tile: copy pre-packed Ws (half 0) or Wr (half 1)
    const uint32_t* W = g_Wh + half * 64 * BS2_STRIDE;
#pragma unroll
    for (int it = 0; it < 8; ++it) {
        int idx = tid + it * 256;
        int kp  = idx >> 5;
        int o4  = idx & 31;
        uint4 v = *(const uint4*)(W + kp * BS2_STRIDE + o4 * 4);
        *(uint4*)(Bs2 + kp * BS2_STRIDE + o4 * 4) = v;
    }

    // A tile: x rows (zero-pad tail); half 0 also preloads out = x
#pragma unroll
    for (int it = 0; it < 8; ++it) {
        int idx = tid + it * 256;
        int m   = idx >> 5;
        int kg  = idx & 31;
        int n   = m0 + m;
        float4 v = make_float4(0.f, 0.f, 0.f, 0.f);
        if (n < N_NODES) {
            v = *(const float4*)(x + (size_t)n * H + kg * 4);
            if (half == 0) *(float4*)(out + (size_t)n * H + kg * 4) = v;
        }
        uint32_t* dst = As2 + m * AS2_STRIDE + kg * 2;
        dst[0] = pack_h2(v.x, v.y);
        dst[1] = pack_h2(v.z, v.w);
    }
    __syncthreads();

    const int lane = tid & 31;
    const int wid  = tid >> 5;
    const int g    = lane >> 2;
    const int tig  = lane & 3;
    const int m_base = (wid & 3) * 16;
    const int n_base = (wid >> 2) * 64;

    float d[8][4];
#pragma unroll
    for (int j = 0; j < 8; ++j)
#pragma unroll
        for (int i = 0; i < 4; ++i) d[j][i] = 0.f;

#pragma unroll
    for (int ks = 0; ks < 8; ++ks) {
        const int kp0 = ks * 8;
        const uint32_t* ar = As2 + (m_base + g) * AS2_STRIDE + kp0 + tig;
        uint32_t a0 = ar[0];
        uint32_t a2 = ar[4];
        uint32_t a1 = ar[8 * AS2_STRIDE];
        uint32_t a3 = ar[8 * AS2_STRIDE + 4];
        const uint32_t* br = Bs2 + (kp0 + tig) * BS2_STRIDE + n_base + g;
#pragma unroll
        for (int j = 0; j < 8; ++j) {
            uint32_t b0 = br[j * 8];
            uint32_t b1v = br[4 * BS2_STRIDE + j * 8];
            mma_f16(d[j], a0, a1, a2, a3, b0, b1v);
        }
    }
    __syncthreads();

    float* Cs = smem_dyn;   // [64][CS_STRIDE]
#pragma unroll
    for (int j = 0; j < 8; ++j) {
        int c = n_base + j * 8 + 2 * tig;
        *(float2*)(Cs + (m_base + g) * CS_STRIDE + c)     = make_float2(d[j][0], d[j][1]);
        *(float2*)(Cs + (m_base + g + 8) * CS_STRIDE + c) = make_float2(d[j][2], d[j][3]);
    }
    __syncthreads();

    // Epilogue: add bias (half 0), pack fp16, store to g_PQh
    const int eg = tid >> 5;
    const int og = tid & 31;
    float4 bias = make_float4(0.f, 0.f, 0.f, 0.f);
    if (half == 0) bias = *(const float4*)(b1 + og * 4);

#pragma unroll
    for (int i = 0; i < 8; ++i) {
        int el = eg * 8 + i;
        int n  = m0 + el;
        if (n < N_NODES) {
            float4 v = *(const float4*)(Cs + el * CS_STRIDE + og * 4);
            v.x += bias.x; v.y += bias.y; v.z += bias.z; v.w += bias.w;
            uint2 u;
            u.x = pack_h2(v.x, v.y);
            u.y = pack_h2(v.z, v.w);
            *(uint2*)(g_PQh + (size_t)n * 128 + half * 64 + og * 2) = u;
        }
    }
}

// ---------------------------------------------------------------------------
// Kernel 2: edge GEMM on fp16 tensor cores (mma.m16n8k16, fp32 accumulate).
// Epilogue: stage accum -> SMEM, gather fp16 P[s]/Q[r], relu, red.v4.
// ---------------------------------------------------------------------------
__global__ __launch_bounds__(256) void edge_kernel(const float* __restrict__ ef,
                                                   const int* __restrict__ senders,
                                                   const int* __restrict__ receivers,
                                                   float* __restrict__ out) {
    extern __shared__ float smem_dyn[];
    uint32_t* As2 = (uint32_t*)smem_dyn;
    uint32_t* Bs2 = (uint32_t*)smem_dyn + 64 * AS2_STRIDE;

    const int tid = threadIdx.x;
    const int e0  = blockIdx.x * 64;

    // B tile: straight copy of pre-packed We (section 2)
    const uint32_t* W = g_Wh + 2 * 64 * BS2_STRIDE;
#pragma unroll
    for (int it = 0; it < 8; ++it) {
        int idx = tid + it * 256;
        int kp  = idx >> 5;
        int o4  = idx & 31;
        uint4 v = *(const uint4*)(W + kp * BS2_STRIDE + o4 * 4);
        *(uint4*)(Bs2 + kp * BS2_STRIDE + o4 * 4) = v;
    }

    // A tile: edge_feat rows, fp16 k-pairs
#pragma unroll
    for (int it = 0; it < 8; ++it) {
        int idx = tid + it * 256;
        int e   = idx >> 5;
        int kg  = idx & 31;
        float4 v = *(const float4*)(ef + (size_t)(e0 + e) * H + kg * 4);
        uint32_t* dst = As2 + e * AS2_STRIDE + kg * 2;
        dst[0] = pack_h2(v.x, v.y);
        dst[1] = pack_h2(v.z, v.w);
    }
    __syncthreads();

    const int lane = tid & 31;
    const int wid  = tid >> 5;
    const int g    = lane >> 2;
    const int tig  = lane & 3;
    const int m_base = (wid & 3) * 16;
    const int n_base = (wid >> 2) * 64;

    float d[8][4];
#pragma unroll
    for (int j = 0; j < 8; ++j)
#pragma unroll
        for (int i = 0; i < 4; ++i) d[j][i] = 0.f;

#pragma unroll
    for (int ks = 0; ks < 8; ++ks) {
        const int kp0 = ks * 8;
        const uint32_t* ar = As2 + (m_base + g) * AS2_STRIDE + kp0 + tig;
        uint32_t a0 = ar[0];
        uint32_t a2 = ar[4];
        uint32_t a1 = ar[8 * AS2_STRIDE];
        uint32_t a3 = ar[8 * AS2_STRIDE + 4];
        const uint32_t* br = Bs2 + (kp0 + tig) * BS2_STRIDE + n_base + g;
#pragma unroll
        for (int j = 0; j < 8; ++j) {
            uint32_t b0 = br[j * 8];
            uint32_t b1v = br[4 * BS2_STRIDE + j * 8];
            mma_f16(d[j], a0, a1, a2, a3, b0, b1v);
        }
    }
    __syncthreads();

    float* Cs = smem_dyn;   // [64][CS_STRIDE]
#pragma unroll
    for (int j = 0; j < 8; ++j) {
        int c = n_base + j * 8 + 2 * tig;
        *(float2*)(Cs + (m_base + g) * CS_STRIDE + c)     = make_float2(d[j][0], d[j][1]);
        *(float2*)(Cs + (m_base + g + 8) * CS_STRIDE + c) = make_float2(d[j][2], d[j][3]);
    }
    __syncthreads();

    // Epilogue: msg = relu(Cs + P[s] + Q[r]); vector-atomic scatter into out[r]
    const int eg = tid >> 5;
    const int og = tid & 31;
#pragma unroll
    for (int i = 0; i < 8; ++i) {
        int el = eg * 8 + i;
        int e  = e0 + el;
        int s  = senders[e];
        int r  = receivers[e];
        float4 m = *(const float4*)(Cs + el * CS_STRIDE + og * 4);
        uint2 pu = *(const uint2*)(g_PQh + (size_t)s * 128 + og * 2);
        uint2 qu = *(const uint2*)(g_PQh + (size_t)r * 128 + 64 + og * 2);
        float2 p0 = h2f2(pu.x), p1 = h2f2(pu.y);
        float2 q0 = h2f2(qu.x), q1 = h2f2(qu.y);
        m.x = fmaxf(m.x + p0.x + q0.x, 0.f);
        m.y = fmaxf(m.y + p0.y + q0.y, 0.f);
        m.z = fmaxf(m.z + p1.x + q1.x, 0.f);
        m.w = fmaxf(m.w + p1.y + q1.y, 0.f);
        float* dst = out + (size_t)r * H + og * 4;
        asm volatile("red.global.add.v4.f32 [%0], {%1,%2,%3,%4};"
                     :: "l"(dst), "f"(m.x), "f"(m.y), "f"(m.z), "f"(m.w)
                     : "memory");
    }
}

// ---------------------------------------------------------------------------
// Kernel 3: in-place LayerNorm, one warp per row
// ---------------------------------------------------------------------------
__global__ __launch_bounds__(256) void ln_kernel(float* __restrict__ out,
                                                 const float* __restrict__ gamma,
                                                 const float* __restrict__ beta) {
    int warp = threadIdx.x >> 5;
    int lane = threadIdx.x & 31;
    int row  = blockIdx.x * 8 + warp;
    if (row >= N_NODES) return;

    float4 h = *(const float4*)(out + (size_t)row * H + lane * 4);
    float s  = h.x + h.y + h.z + h.w;
    float s2 = h.x * h.x + h.y * h.y + h.z * h.z + h.w * h.w;
#pragma unroll
    for (int off = 16; off > 0; off >>= 1) {
        s  += __shfl_xor_sync(0xffffffffu, s, off);
        s2 += __shfl_xor_sync(0xffffffffu, s2, off);
    }
    float mean = s * (1.f / H);
    float var  = s2 * (1.f / H) - mean * mean;
    float rstd = rsqrtf(var + LN_EPS);

    float4 g = *(const float4*)(gamma + lane * 4);
    float4 b = *(const float4*)(beta + lane * 4);
    float4 o;
    o.x = g.x * (h.x - mean) * rstd + b.x;
    o.y = g.y * (h.y - mean) * rstd + b.y;
    o.z = g.z * (h.z - mean) * rstd + b.z;
    o.w = g.w * (h.w - mean) * rstd + b.w;
    *(float4*)(out + (size_t)row * H + lane * 4) = o;
}

// ---------------------------------------------------------------------------
extern "C" void kernel_launch(void* const* d_in, const int* in_sizes, int n_in,
                              void* d_out, int out_size) {
    const float* x         = (const float*)d_in[0];
    const int*   senders   = (const int*)d_in[1];
    const int*   receivers = (const int*)d_in[2];
    const float* ef        = (const float*)d_in[3];
    const float* W1        = (const float*)d_in[4];
    const float* b1        = (const float*)d_in[5];
    const float* gamma     = (const float*)d_in[6];
    const float* beta      = (const float*)d_in[7];
    float*       out       = (float*)d_out;

    cudaFuncSetAttribute(edge_kernel, cudaFuncAttributeMaxDynamicSharedMemorySize,
                         SMEM_EDGE);
    cudaFuncSetAttribute(proj_kernel, cudaFuncAttributeMaxDynamicSharedMemorySize,
                         SMEM_EDGE);

    pack_w_kernel<<<1, 256>>>(W1);
    proj_kernel<<<dim3((N_NODES + 63) / 64, 2), 256, SMEM_EDGE>>>(x, b1, out);
    edge_kernel<<<N_EDGES / 64, 256, SMEM_EDGE>>>(ef, senders, receivers, out);
    ln_kernel<<<N_NODES / 8, 256>>>(out, gamma, beta);
}